// round 3
// baseline (speedup 1.0000x reference)
#include <cuda_runtime.h>
#include <cstdint>

#define NN    50000
#define INF   64
#define LD    128
#define NSTEP 3
#define TT    4
#define EE    800000

// -------- scratch (static device globals; 16B-aligned for float4 access) ---
__device__ __align__(16) float g_x0 [(size_t)NN * LD];
__device__ __align__(16) float g_gh [(size_t)NN * 3 * LD];
__device__ __align__(16) float g_H  [(size_t)TT * NN * LD];
__device__ __align__(16) float g_agg[(size_t)NN * LD];
__device__ __align__(16) float g_gi [(size_t)NN * 3 * LD];
__device__ __align__(16) float g_m  [(size_t)NN * LD];
__device__ int g_src [EE];
__device__ int g_dst [EE];
__device__ int g_bond[EE];

// --------------------------------------------------------------------------
// Edge preprocessing. Handles edge_index as int32 OR int64 (detected from
// the data: all indices < 50000, so an int64 buffer has zero odd words).
// argmax(edge_attr) -> bond type. Reference's tile(...,(1,2)) duplicates
// edges exactly -> keep E edges, apply factor 2 in the scatter.
// --------------------------------------------------------------------------
__global__ void prep_edges(const void* __restrict__ ei_raw,
                           const float* __restrict__ attr,
                           int* __restrict__ src, int* __restrict__ dst,
                           int* __restrict__ bond)
{
    int e = blockIdx.x * blockDim.x + threadIdx.x;
    if (e >= EE) return;

    const int*       ei32 = (const int*)ei_raw;
    const long long* ei64 = (const long long*)ei_raw;

    // dtype sniff: if int64 little-endian with values < 2^31, every odd
    // 32-bit word is zero. Random int32 indices in [0,50000) make 32
    // consecutive zero odd-words essentially impossible.
    bool is64 = true;
#pragma unroll
    for (int i = 1; i < 64; i += 2)
        if (ei32[i] != 0) { is64 = false; break; }

    long long s, d;
    if (is64) { s = ei64[e]; d = ei64[(size_t)EE + e]; }
    else      { s = ei32[e]; d = ei32[EE + e]; }
    src[e] = (s >= 0 && s < NN) ? (int)s : 0;
    dst[e] = (d >= 0 && d < NN) ? (int)d : 0;

    float4 a = *reinterpret_cast<const float4*>(attr + 4 * (size_t)e);
    int b = 0; float best = a.x;
    if (a.y > best) { best = a.y; b = 1; }
    if (a.z > best) { best = a.z; b = 2; }
    if (a.w > best) { best = a.w; b = 3; }
    bond[e] = b;
}

// --------------------------------------------------------------------------
// SGEMM: C[n][m] = act( sum_k A[n][k] * B[m][k] + bias[m] )   (A @ B^T)
// 128x128 block tile, 8x8 per thread, 256 threads, K staged in chunks of 8.
// blockIdx.z batches over B (stride strideB) and C (stride strideC).
// --------------------------------------------------------------------------
template<bool RELU>
__global__ __launch_bounds__(256)
void sgemm(const float* __restrict__ A, const float* __restrict__ Bbase,
           const float* __restrict__ bias, float* __restrict__ Cbase,
           int nrows, int M, int K, long strideB, long strideC)
{
    const float* B = Bbase + (size_t)blockIdx.z * strideB;
    float*       C = Cbase + (size_t)blockIdx.z * strideC;

    __shared__ float As[8][128];
    __shared__ float Bs[8][128];

    const int tid  = threadIdx.x;
    const int tx   = tid & 15;       // 0..15  -> 8 output cols each
    const int ty   = tid >> 4;       // 0..15  -> 8 output rows each
    const int row0 = blockIdx.y * 128;
    const int col0 = blockIdx.x * 128;

    float acc[8][8];
#pragma unroll
    for (int i = 0; i < 8; i++)
#pragma unroll
        for (int j = 0; j < 8; j++) acc[i][j] = 0.f;

    const int lr = tid >> 1;          // 0..127 tile row
    const int lk = (tid & 1) * 4;     // 0 or 4 within K-chunk

    for (int k0 = 0; k0 < K; k0 += 8) {
        int ar = row0 + lr;
        float4 av = make_float4(0.f, 0.f, 0.f, 0.f);
        if (ar < nrows)
            av = *reinterpret_cast<const float4*>(A + (size_t)ar * K + k0 + lk);
        As[lk + 0][lr] = av.x; As[lk + 1][lr] = av.y;
        As[lk + 2][lr] = av.z; As[lk + 3][lr] = av.w;

        float4 bv = *reinterpret_cast<const float4*>(B + (size_t)(col0 + lr) * K + k0 + lk);
        Bs[lk + 0][lr] = bv.x; Bs[lk + 1][lr] = bv.y;
        Bs[lk + 2][lr] = bv.z; Bs[lk + 3][lr] = bv.w;

        __syncthreads();

#pragma unroll
        for (int k = 0; k < 8; k++) {
            float4 a0 = *reinterpret_cast<const float4*>(&As[k][ty * 8]);
            float4 a1 = *reinterpret_cast<const float4*>(&As[k][ty * 8 + 4]);
            float4 b0 = *reinterpret_cast<const float4*>(&Bs[k][tx * 8]);
            float4 b1 = *reinterpret_cast<const float4*>(&Bs[k][tx * 8 + 4]);
            float a[8] = {a0.x, a0.y, a0.z, a0.w, a1.x, a1.y, a1.z, a1.w};
            float b[8] = {b0.x, b0.y, b0.z, b0.w, b1.x, b1.y, b1.z, b1.w};
#pragma unroll
            for (int i = 0; i < 8; i++)
#pragma unroll
                for (int j = 0; j < 8; j++)
                    acc[i][j] = fmaf(a[i], b[j], acc[i][j]);
        }
        __syncthreads();
    }

#pragma unroll
    for (int i = 0; i < 8; i++) {
        int r = row0 + ty * 8 + i;
        if (r >= nrows) continue;
#pragma unroll
        for (int j = 0; j < 8; j++) {
            int c = col0 + tx * 8 + j;
            float v = acc[i][j] + (bias ? bias[c] : 0.f);
            if (RELU) v = fmaxf(v, 0.f);
            C[(size_t)r * M + c] = v;
        }
    }
}

// --------------------------------------------------------------------------
// Scatter: one warp per edge. agg[dst] += 2 * H[bond][src]
// Row = 128 floats = 32 lanes x float4. Vector reduction (sm_90+).
// --------------------------------------------------------------------------
__global__ void scatter_edges(const float4* __restrict__ H,
                              const int* __restrict__ src,
                              const int* __restrict__ dst,
                              const int* __restrict__ bond,
                              float* __restrict__ agg)
{
    int warp = (blockIdx.x * blockDim.x + threadIdx.x) >> 5;
    int lane = threadIdx.x & 31;
    if (warp >= EE) return;
    int s = src[warp], d = dst[warp], b = bond[warp];
    float4 v = __ldg(&H[((size_t)b * NN + s) * 32 + lane]);
    float* p = agg + (size_t)d * 128 + lane * 4;
    asm volatile("red.global.add.v4.f32 [%0], {%1,%2,%3,%4};"
                 :: "l"(p), "f"(2.f * v.x), "f"(2.f * v.y),
                    "f"(2.f * v.z), "f"(2.f * v.w)
                 : "memory");
}

// --------------------------------------------------------------------------
// GRU cell (hidden = x0 always) + relu.
// --------------------------------------------------------------------------
__device__ __forceinline__ float sigm(float x) { return 1.f / (1.f + __expf(-x)); }

__global__ void gru_relu(const float* __restrict__ gi,
                         const float* __restrict__ gh,
                         const float* __restrict__ x0,
                         float* __restrict__ m)
{
    int i = blockIdx.x * blockDim.x + threadIdx.x;
    if (i >= NN * LD) return;
    int n = i >> 7, j = i & 127;
    const float* gin = gi + (size_t)n * 3 * LD;
    const float* ghn = gh + (size_t)n * 3 * LD;
    float r  = sigm(gin[j]          + ghn[j]);
    float z  = sigm(gin[LD + j]     + ghn[LD + j]);
    float ng = tanhf(gin[2 * LD + j] + r * ghn[2 * LD + j]);
    float h  = x0[i];
    float v  = (1.f - z) * ng + z * h;
    m[i] = fmaxf(v, 0.f);
}

// --------------------------------------------------------------------------
extern "C" void kernel_launch(void* const* d_in, const int* in_sizes, int n_in,
                              void* d_out, int out_size)
{
    const float* x     = (const float*)d_in[0];
    const void*  ei    = d_in[1];                  // int32 or int64; detected on device
    const float* attr  = (const float*)d_in[2];
    const float* lin_w = (const float*)d_in[3];
    const float* lin_b = (const float*)d_in[4];
    const float* gnn_w = (const float*)d_in[5];
    const float* w_ih  = (const float*)d_in[6];
    const float* w_hh  = (const float*)d_in[7];
    const float* b_ih  = (const float*)d_in[8];
    const float* b_hh  = (const float*)d_in[9];
    const float* mu_w  = (const float*)d_in[10];
    const float* mu_b  = (const float*)d_in[11];
    const float* lv_w  = (const float*)d_in[12];
    const float* lv_b  = (const float*)d_in[13];
    float* out = (float*)d_out;

    float *x0, *gh, *H, *agg, *gi, *m;
    int *src, *dst, *bond;
    cudaGetSymbolAddress((void**)&x0,  g_x0);
    cudaGetSymbolAddress((void**)&gh,  g_gh);
    cudaGetSymbolAddress((void**)&H,   g_H);
    cudaGetSymbolAddress((void**)&agg, g_agg);
    cudaGetSymbolAddress((void**)&gi,  g_gi);
    cudaGetSymbolAddress((void**)&m,   g_m);
    cudaGetSymbolAddress((void**)&src, g_src);
    cudaGetSymbolAddress((void**)&dst, g_dst);
    cudaGetSymbolAddress((void**)&bond,g_bond);

    const int YB = (NN + 127) / 128;   // 391

    prep_edges<<<(EE + 255) / 256, 256>>>(ei, attr, src, dst, bond);

    // x0 = relu(x @ lin_w.T + lin_b)           [N,128], K=64
    sgemm<true ><<<dim3(1, YB, 1), 256>>>(x,  lin_w, lin_b, x0, NN, LD,     INF, 0, 0);
    // gh = x0 @ w_hh.T + b_hh  (loop invariant) [N,384], K=128
    sgemm<false><<<dim3(3, YB, 1), 256>>>(x0, w_hh,  b_hh,  gh, NN, 3 * LD, LD,  0, 0);

    for (int s = 0; s < NSTEP; s++) {
        const float* mIn = (s == 0) ? x0 : m;
        // H[t] = mIn @ gnn_w[s][t].T  (batched over t)
        sgemm<false><<<dim3(1, YB, TT), 256>>>(
            mIn, gnn_w + (size_t)s * TT * LD * LD, nullptr, H,
            NN, LD, LD, (long)LD * LD, (long)NN * LD);

        cudaMemsetAsync(agg, 0, (size_t)NN * LD * sizeof(float));
        scatter_edges<<<(EE + 7) / 8, 256>>>((const float4*)H, src, dst, bond, agg);

        // gi = agg @ w_ih.T + b_ih   [N,384]
        sgemm<false><<<dim3(3, YB, 1), 256>>>(agg, w_ih, b_ih, gi, NN, 3 * LD, LD, 0, 0);
        gru_relu<<<(NN * LD + 255) / 256, 256>>>(gi, gh, x0, m);
    }

    // mu / logvar heads -> out[0:N*L], out[N*L:2*N*L]
    sgemm<false><<<dim3(1, YB, 1), 256>>>(m, mu_w, mu_b, out,                   NN, LD, LD, 0, 0);
    sgemm<false><<<dim3(1, YB, 1), 256>>>(m, lv_w, lv_b, out + (size_t)NN * LD, NN, LD, LD, 0, 0);
}

// round 8
// speedup vs baseline: 1.8270x; 1.8270x over previous
#include <cuda_runtime.h>
#include <cuda_bf16.h>
#include <cstdint>

#define NN    50000
#define INF   64
#define LD    128
#define NSTEP 3
#define TT    4
#define EE    800000

// -------- scratch (static device globals; 16B-aligned for float4 access) ---
__device__ __align__(16) float g_x0 [(size_t)NN * LD];
__device__ __align__(16) float g_gh [(size_t)NN * 3 * LD];
__device__ __align__(16) float g_H  [(size_t)TT * NN * LD];
__device__ __align__(16) float g_agg[(size_t)NN * LD];
__device__ __align__(16) float g_gi [(size_t)NN * 3 * LD];
__device__ __align__(16) float g_m  [(size_t)NN * LD];
__device__ int g_src [EE];
__device__ int g_dst [EE];
__device__ int g_bond[EE];

// --------------------------------------------------------------------------
// Edge preprocessing. Handles edge_index as int32 OR int64 (detected from
// data: indices < 50000 => an int64 buffer has all-zero odd 32-bit words).
// argmax(edge_attr) -> bond type. The reference's tile(...,(1,2)) duplicates
// each edge exactly -> keep E edges, apply factor 2 in the scatter.
// --------------------------------------------------------------------------
__global__ void prep_edges(const void* __restrict__ ei_raw,
                           const float* __restrict__ attr,
                           int* __restrict__ src, int* __restrict__ dst,
                           int* __restrict__ bond)
{
    int e = blockIdx.x * blockDim.x + threadIdx.x;
    if (e >= EE) return;

    const int*       ei32 = (const int*)ei_raw;
    const long long* ei64 = (const long long*)ei_raw;

    bool is64 = true;
#pragma unroll
    for (int i = 1; i < 64; i += 2)
        if (ei32[i] != 0) { is64 = false; break; }

    long long s, d;
    if (is64) { s = ei64[e]; d = ei64[(size_t)EE + e]; }
    else      { s = ei32[e]; d = ei32[EE + e]; }
    src[e] = (s >= 0 && s < NN) ? (int)s : 0;
    dst[e] = (d >= 0 && d < NN) ? (int)d : 0;

    float4 a = *reinterpret_cast<const float4*>(attr + 4 * (size_t)e);
    int b = 0; float best = a.x;
    if (a.y > best) { best = a.y; b = 1; }
    if (a.z > best) { best = a.z; b = 2; }
    if (a.w > best) { best = a.w; b = 3; }
    bond[e] = b;
}

// --------------------------------------------------------------------------
// Tensor-core GEMM: C = act(A @ B^T + bias), split-bf16 (3-term) for ~fp32
// accuracy. A [nrows x K] row-major, B [M x K] row-major, z batches B and C.
// 128x128 block tile, 8 warps (32x64 each), BK=32, mma.m16n8k16.bf16.
// --------------------------------------------------------------------------
__device__ __forceinline__ void ldsm_x4(uint32_t& r0, uint32_t& r1,
                                        uint32_t& r2, uint32_t& r3,
                                        const void* p)
{
    uint32_t addr = (uint32_t)__cvta_generic_to_shared(p);
    asm volatile("ldmatrix.sync.aligned.m8n8.x4.shared.b16 {%0,%1,%2,%3}, [%4];"
                 : "=r"(r0), "=r"(r1), "=r"(r2), "=r"(r3) : "r"(addr));
}

__device__ __forceinline__ void mma_bf16(float* c, const uint32_t* a, const uint32_t* b)
{
    asm volatile("mma.sync.aligned.m16n8k16.row.col.f32.bf16.bf16.f32 "
                 "{%0,%1,%2,%3}, {%4,%5,%6,%7}, {%8,%9}, {%0,%1,%2,%3};"
                 : "+f"(c[0]), "+f"(c[1]), "+f"(c[2]), "+f"(c[3])
                 : "r"(a[0]), "r"(a[1]), "r"(a[2]), "r"(a[3]),
                   "r"(b[0]), "r"(b[1]));
}

template<bool RELU>
__global__ __launch_bounds__(256)
void tgemm(const float* __restrict__ A, const float* __restrict__ Bbase,
           const float* __restrict__ bias, float* __restrict__ Cbase,
           int nrows, int M, int K, long strideB, long strideC)
{
    const float* Bg = Bbase + (size_t)blockIdx.z * strideB;
    float*       C  = Cbase + (size_t)blockIdx.z * strideC;

    // pitch 40 halves => conflict-reduced ldmatrix row distribution
    __shared__ __align__(16) __nv_bfloat16 As[2][128][40];  // [hi/lo][m][k]
    __shared__ __align__(16) __nv_bfloat16 Bs[2][128][40];  // [hi/lo][n][k]

    const int tid  = threadIdx.x;
    const int lane = tid & 31;
    const int wid  = tid >> 5;
    const int wm   = wid >> 1;                 // 0..3  -> m offset wm*32
    const int wn   = wid & 1;                  // 0..1  -> n offset wn*64
    const int row0 = blockIdx.y * 128;
    const int col0 = blockIdx.x * 128;

    float acc[2][8][4];
#pragma unroll
    for (int mt = 0; mt < 2; mt++)
#pragma unroll
        for (int nt = 0; nt < 8; nt++)
#pragma unroll
            for (int i = 0; i < 4; i++) acc[mt][nt][i] = 0.f;

    const int srow = tid >> 1;           // 0..127
    const int skq  = (tid & 1) * 16;     // 0 or 16

    for (int k0 = 0; k0 < K; k0 += 32) {
        // ---- stage A (guarded rows) and B into hi/lo bf16 smem planes ----
        {
            int gr = row0 + srow;
            const float* ap = A + (size_t)gr * K + k0 + skq;
#pragma unroll
            for (int i = 0; i < 4; i++) {
                float4 v = (gr < nrows) ? *(const float4*)(ap + i * 4)
                                        : make_float4(0.f, 0.f, 0.f, 0.f);
                float f[4] = {v.x, v.y, v.z, v.w};
                __nv_bfloat16 h[4], l[4];
#pragma unroll
                for (int j = 0; j < 4; j++) {
                    h[j] = __float2bfloat16_rn(f[j]);
                    l[j] = __float2bfloat16_rn(f[j] - __bfloat162float(h[j]));
                }
                int kk = skq + i * 4;
                *(__nv_bfloat162*)&As[0][srow][kk]     = __halves2bfloat162(h[0], h[1]);
                *(__nv_bfloat162*)&As[0][srow][kk + 2] = __halves2bfloat162(h[2], h[3]);
                *(__nv_bfloat162*)&As[1][srow][kk]     = __halves2bfloat162(l[0], l[1]);
                *(__nv_bfloat162*)&As[1][srow][kk + 2] = __halves2bfloat162(l[2], l[3]);
            }
            const float* bp = Bg + (size_t)(col0 + srow) * K + k0 + skq;
#pragma unroll
            for (int i = 0; i < 4; i++) {
                float4 v = *(const float4*)(bp + i * 4);
                float f[4] = {v.x, v.y, v.z, v.w};
                __nv_bfloat16 h[4], l[4];
#pragma unroll
                for (int j = 0; j < 4; j++) {
                    h[j] = __float2bfloat16_rn(f[j]);
                    l[j] = __float2bfloat16_rn(f[j] - __bfloat162float(h[j]));
                }
                int kk = skq + i * 4;
                *(__nv_bfloat162*)&Bs[0][srow][kk]     = __halves2bfloat162(h[0], h[1]);
                *(__nv_bfloat162*)&Bs[0][srow][kk + 2] = __halves2bfloat162(h[2], h[3]);
                *(__nv_bfloat162*)&Bs[1][srow][kk]     = __halves2bfloat162(l[0], l[1]);
                *(__nv_bfloat162*)&Bs[1][srow][kk + 2] = __halves2bfloat162(l[2], l[3]);
            }
        }
        __syncthreads();

        // ---- compute: two k16 steps ----
#pragma unroll
        for (int kk = 0; kk < 2; kk++) {
            uint32_t af[2][2][4];   // [plane][mtile]
#pragma unroll
            for (int mt = 0; mt < 2; mt++) {
                int r = wm * 32 + mt * 16 + (lane & 15);
                int c = kk * 16 + ((lane >> 4) << 3);
                ldsm_x4(af[0][mt][0], af[0][mt][1], af[0][mt][2], af[0][mt][3], &As[0][r][c]);
                ldsm_x4(af[1][mt][0], af[1][mt][1], af[1][mt][2], af[1][mt][3], &As[1][r][c]);
            }
            uint32_t bfr[2][4][4];  // [plane][ngroup of 2 ntiles]
#pragma unroll
            for (int ng = 0; ng < 4; ng++) {
                int r = wn * 64 + ng * 16 + ((lane >> 4) << 3) + (lane & 7);
                int c = kk * 16 + ((lane >> 3) & 1) * 8;
                ldsm_x4(bfr[0][ng][0], bfr[0][ng][1], bfr[0][ng][2], bfr[0][ng][3], &Bs[0][r][c]);
                ldsm_x4(bfr[1][ng][0], bfr[1][ng][1], bfr[1][ng][2], bfr[1][ng][3], &Bs[1][r][c]);
            }
#pragma unroll
            for (int mt = 0; mt < 2; mt++)
#pragma unroll
                for (int ng = 0; ng < 4; ng++)
#pragma unroll
                    for (int h = 0; h < 2; h++) {
                        int nt = ng * 2 + h;
                        mma_bf16(acc[mt][nt], af[0][mt], &bfr[0][ng][h * 2]); // Ah*Bh
                        mma_bf16(acc[mt][nt], af[0][mt], &bfr[1][ng][h * 2]); // Ah*Bl
                        mma_bf16(acc[mt][nt], af[1][mt], &bfr[0][ng][h * 2]); // Al*Bh
                    }
        }
        __syncthreads();
    }

    // ---- epilogue: bias + optional relu, guarded rows ----
#pragma unroll
    for (int mt = 0; mt < 2; mt++) {
        int rbase = row0 + wm * 32 + mt * 16 + (lane >> 2);
#pragma unroll
        for (int nt = 0; nt < 8; nt++) {
            int c = col0 + wn * 64 + nt * 8 + (lane & 3) * 2;
            float b0 = bias ? bias[c]     : 0.f;
            float b1 = bias ? bias[c + 1] : 0.f;
            float v0 = acc[mt][nt][0] + b0, v1 = acc[mt][nt][1] + b1;
            float v2 = acc[mt][nt][2] + b0, v3 = acc[mt][nt][3] + b1;
            if (RELU) {
                v0 = fmaxf(v0, 0.f); v1 = fmaxf(v1, 0.f);
                v2 = fmaxf(v2, 0.f); v3 = fmaxf(v3, 0.f);
            }
            if (rbase < nrows)
                *(float2*)&C[(size_t)rbase * M + c] = make_float2(v0, v1);
            if (rbase + 8 < nrows)
                *(float2*)&C[(size_t)(rbase + 8) * M + c] = make_float2(v2, v3);
        }
    }
}

// --------------------------------------------------------------------------
// Scatter: one warp per edge. agg[dst] += 2 * H[bond][src]
// --------------------------------------------------------------------------
__global__ void scatter_edges(const float4* __restrict__ H,
                              const int* __restrict__ src,
                              const int* __restrict__ dst,
                              const int* __restrict__ bond,
                              float* __restrict__ agg)
{
    int warp = (blockIdx.x * blockDim.x + threadIdx.x) >> 5;
    int lane = threadIdx.x & 31;
    if (warp >= EE) return;
    int s = src[warp], d = dst[warp], b = bond[warp];
    float4 v = __ldg(&H[((size_t)b * NN + s) * 32 + lane]);
    float* p = agg + (size_t)d * 128 + lane * 4;
    asm volatile("red.global.add.v4.f32 [%0], {%1,%2,%3,%4};"
                 :: "l"(p), "f"(2.f * v.x), "f"(2.f * v.y),
                    "f"(2.f * v.z), "f"(2.f * v.w)
                 : "memory");
}

// --------------------------------------------------------------------------
// GRU cell (hidden = x0 always) + relu.
// --------------------------------------------------------------------------
__device__ __forceinline__ float sigm(float x) { return 1.f / (1.f + __expf(-x)); }

__global__ void gru_relu(const float* __restrict__ gi,
                         const float* __restrict__ gh,
                         const float* __restrict__ x0,
                         float* __restrict__ m)
{
    int i = blockIdx.x * blockDim.x + threadIdx.x;
    if (i >= NN * LD) return;
    int n = i >> 7, j = i & 127;
    const float* gin = gi + (size_t)n * 3 * LD;
    const float* ghn = gh + (size_t)n * 3 * LD;
    float r  = sigm(gin[j]          + ghn[j]);
    float z  = sigm(gin[LD + j]     + ghn[LD + j]);
    float ng = tanhf(gin[2 * LD + j] + r * ghn[2 * LD + j]);
    float h  = x0[i];
    float v  = (1.f - z) * ng + z * h;
    m[i] = fmaxf(v, 0.f);
}

// --------------------------------------------------------------------------
extern "C" void kernel_launch(void* const* d_in, const int* in_sizes, int n_in,
                              void* d_out, int out_size)
{
    const float* x     = (const float*)d_in[0];
    const void*  ei    = d_in[1];                  // int32 or int64; detected on device
    const float* attr  = (const float*)d_in[2];
    const float* lin_w = (const float*)d_in[3];
    const float* lin_b = (const float*)d_in[4];
    const float* gnn_w = (const float*)d_in[5];
    const float* w_ih  = (const float*)d_in[6];
    const float* w_hh  = (const float*)d_in[7];
    const float* b_ih  = (const float*)d_in[8];
    const float* b_hh  = (const float*)d_in[9];
    const float* mu_w  = (const float*)d_in[10];
    const float* mu_b  = (const float*)d_in[11];
    const float* lv_w  = (const float*)d_in[12];
    const float* lv_b  = (const float*)d_in[13];
    float* out = (float*)d_out;

    float *x0, *gh, *H, *agg, *gi, *m;
    int *src, *dst, *bond;
    cudaGetSymbolAddress((void**)&x0,  g_x0);
    cudaGetSymbolAddress((void**)&gh,  g_gh);
    cudaGetSymbolAddress((void**)&H,   g_H);
    cudaGetSymbolAddress((void**)&agg, g_agg);
    cudaGetSymbolAddress((void**)&gi,  g_gi);
    cudaGetSymbolAddress((void**)&m,   g_m);
    cudaGetSymbolAddress((void**)&src, g_src);
    cudaGetSymbolAddress((void**)&dst, g_dst);
    cudaGetSymbolAddress((void**)&bond,g_bond);

    const int YB = (NN + 127) / 128;   // 391

    prep_edges<<<(EE + 255) / 256, 256>>>(ei, attr, src, dst, bond);

    // x0 = relu(x @ lin_w.T + lin_b)           [N,128], K=64
    tgemm<true ><<<dim3(1, YB, 1), 256>>>(x,  lin_w, lin_b, x0, NN, LD,     INF, 0, 0);
    // gh = x0 @ w_hh.T + b_hh  (loop invariant) [N,384], K=128
    tgemm<false><<<dim3(3, YB, 1), 256>>>(x0, w_hh,  b_hh,  gh, NN, 3 * LD, LD,  0, 0);

    for (int s = 0; s < NSTEP; s++) {
        const float* mIn = (s == 0) ? x0 : m;
        // H[t] = mIn @ gnn_w[s][t].T  (batched over t)
        tgemm<false><<<dim3(1, YB, TT), 256>>>(
            mIn, gnn_w + (size_t)s * TT * LD * LD, nullptr, H,
            NN, LD, LD, (long)LD * LD, (long)NN * LD);

        cudaMemsetAsync(agg, 0, (size_t)NN * LD * sizeof(float));
        scatter_edges<<<(EE + 7) / 8, 256>>>((const float4*)H, src, dst, bond, agg);

        // gi = agg @ w_ih.T + b_ih   [N,384]
        tgemm<false><<<dim3(3, YB, 1), 256>>>(agg, w_ih, b_ih, gi, NN, 3 * LD, LD, 0, 0);
        gru_relu<<<(NN * LD + 255) / 256, 256>>>(gi, gh, x0, m);
    }

    // mu / logvar heads -> out[0:N*L], out[N*L:2*N*L]
    tgemm<false><<<dim3(1, YB, 1), 256>>>(m, mu_w, mu_b, out,                   NN, LD, LD, 0, 0);
    tgemm<false><<<dim3(1, YB, 1), 256>>>(m, lv_w, lv_b, out + (size_t)NN * LD, NN, LD, LD, 0, 0);
}

// round 11
// speedup vs baseline: 1.8730x; 1.0252x over previous
#include <cuda_runtime.h>
#include <cuda_bf16.h>
#include <cstdint>

#define NN    50000
#define INF   64
#define LD    128
#define NSTEP 3
#define TT    4
#define EE    800000

// -------- scratch (static device globals) ----------------------------------
__device__ __align__(16) float g_x0  [(size_t)NN * LD];
__device__ __align__(16) float g_gh  [(size_t)NN * 3 * LD];
__device__ __align__(16) float g_aggT[(size_t)NN * 4 * LD];   // [d][t*128+j]
__device__ __align__(16) float g_agg [(size_t)NN * LD];
__device__ __align__(16) float g_gi  [(size_t)NN * 3 * LD];
__device__ __align__(16) float g_m   [(size_t)NN * LD];
__device__ __align__(16) float g_wcat[(size_t)NSTEP * LD * 4 * LD]; // [s][i][t*128+j]
__device__ int g_src   [EE];
__device__ int g_dst   [EE];
__device__ int g_bond  [EE];
__device__ int g_cnt   [NN];
__device__ int g_rowptr[NN + 1];
__device__ int g_cursor[NN];
__device__ int g_packed[EE];          // src | (bond<<16)

// --------------------------------------------------------------------------
// Edge preprocessing: dtype-robust index decode, bond argmax, dst histogram.
// Reference's tile(...,(1,2)) duplicates edges exactly -> keep E edges,
// apply factor 2 in the aggregation.
// --------------------------------------------------------------------------
__global__ void prep_edges(const void* __restrict__ ei_raw,
                           const float* __restrict__ attr,
                           int* __restrict__ src, int* __restrict__ dst,
                           int* __restrict__ bond, int* __restrict__ cnt)
{
    int e = blockIdx.x * blockDim.x + threadIdx.x;
    if (e >= EE) return;

    const int*       ei32 = (const int*)ei_raw;
    const long long* ei64 = (const long long*)ei_raw;

    bool is64 = true;
#pragma unroll
    for (int i = 1; i < 64; i += 2)
        if (ei32[i] != 0) { is64 = false; break; }

    long long s, d;
    if (is64) { s = ei64[e]; d = ei64[(size_t)EE + e]; }
    else      { s = ei32[e]; d = ei32[EE + e]; }
    int si = (s >= 0 && s < NN) ? (int)s : 0;
    int di = (d >= 0 && d < NN) ? (int)d : 0;
    src[e] = si;
    dst[e] = di;

    float4 a = *reinterpret_cast<const float4*>(attr + 4 * (size_t)e);
    int b = 0; float best = a.x;
    if (a.y > best) { best = a.y; b = 1; }
    if (a.z > best) { best = a.z; b = 2; }
    if (a.w > best) { best = a.w; b = 3; }
    bond[e] = b;

    atomicAdd(&cnt[di], 1);
}

// Exclusive scan of per-node counts -> row_ptr (and cursor copy). One block.
__global__ __launch_bounds__(1024)
void scan_counts(const int* __restrict__ cnt, int* __restrict__ row_ptr,
                 int* __restrict__ cursor)
{
    __shared__ int part[1024];
    const int t  = threadIdx.x;
    const int CH = (NN + 1023) / 1024;
    int lo = t * CH;
    int hi = lo + CH; if (hi > NN) hi = NN; if (lo > NN) lo = NN;

    int s = 0;
    for (int i = lo; i < hi; i++) s += cnt[i];
    part[t] = s;
    __syncthreads();
    for (int off = 1; off < 1024; off <<= 1) {
        int v = (t >= off) ? part[t - off] : 0;
        __syncthreads();
        part[t] += v;
        __syncthreads();
    }
    int run = (t == 0) ? 0 : part[t - 1];
    for (int i = lo; i < hi; i++) {
        row_ptr[i] = run; cursor[i] = run; run += cnt[i];
    }
    if (t == 1023) row_ptr[NN] = part[1023];
}

__global__ void fill_csr(const int* __restrict__ src, const int* __restrict__ dst,
                         const int* __restrict__ bond, int* __restrict__ cursor,
                         int* __restrict__ packed)
{
    int e = blockIdx.x * blockDim.x + threadIdx.x;
    if (e >= EE) return;
    int pos = atomicAdd(&cursor[dst[e]], 1);
    packed[pos] = src[e] | (bond[e] << 16);
}

// Pack gnn_w [s][t][i][j] -> wcat [s][i][t*128+j] (B operand, row-major, K=512)
__global__ void pack_wcat(const float* __restrict__ gnn_w, float* __restrict__ wcat)
{
    int i = blockIdx.x * blockDim.x + threadIdx.x;
    if (i >= NSTEP * LD * 4 * LD) return;
    int s = i / (LD * 4 * LD);
    int r = (i / (4 * LD)) % LD;
    int k = i % (4 * LD);
    int t = k / LD, j = k % LD;
    wcat[i] = gnn_w[(((size_t)s * TT + t) * LD + r) * LD + j];
}

// --------------------------------------------------------------------------
// CSR aggregation: one warp per dst node. Buckets m[src] rows by bond type,
// accumulates in registers, writes aggT[d][t*128+...] with the x2 edge-dup
// factor. No atomics, no memset (every row written).
// --------------------------------------------------------------------------
__global__ void aggregate(const float4* __restrict__ m4,
                          const int* __restrict__ row_ptr,
                          const int* __restrict__ packed,
                          float4* __restrict__ aggT4)
{
    int w    = (blockIdx.x * blockDim.x + threadIdx.x) >> 5;
    int lane = threadIdx.x & 31;
    if (w >= NN) return;
    int e0 = row_ptr[w], e1 = row_ptr[w + 1];

    float4 a0 = {0,0,0,0}, a1 = {0,0,0,0}, a2 = {0,0,0,0}, a3 = {0,0,0,0};

    for (int base = e0; base < e1; base += 32) {
        int idx = base + lane;
        int pe  = (idx < e1) ? packed[idx] : 0;
        int nb  = e1 - base; if (nb > 32) nb = 32;
        for (int i = 0; i < nb; i++) {
            int p = __shfl_sync(0xffffffffu, pe, i);
            int s = p & 0xffff, b = p >> 16;
            float4 v = m4[(size_t)s * 32 + lane];
            if      (b == 0) { a0.x += v.x; a0.y += v.y; a0.z += v.z; a0.w += v.w; }
            else if (b == 1) { a1.x += v.x; a1.y += v.y; a1.z += v.z; a1.w += v.w; }
            else if (b == 2) { a2.x += v.x; a2.y += v.y; a2.z += v.z; a2.w += v.w; }
            else             { a3.x += v.x; a3.y += v.y; a3.z += v.z; a3.w += v.w; }
        }
    }
    float4* o = aggT4 + (size_t)w * 128;    // 512 floats = 128 float4
    o[lane]      = make_float4(2.f*a0.x, 2.f*a0.y, 2.f*a0.z, 2.f*a0.w);
    o[32 + lane] = make_float4(2.f*a1.x, 2.f*a1.y, 2.f*a1.z, 2.f*a1.w);
    o[64 + lane] = make_float4(2.f*a2.x, 2.f*a2.y, 2.f*a2.z, 2.f*a2.w);
    o[96 + lane] = make_float4(2.f*a3.x, 2.f*a3.y, 2.f*a3.z, 2.f*a3.w);
}

// --------------------------------------------------------------------------
// Tensor-core GEMM: C = act(A @ B^T + bias), split-bf16 (3-term). Unchanged
// from the proven R8 kernel.
// --------------------------------------------------------------------------
__device__ __forceinline__ void ldsm_x4(uint32_t& r0, uint32_t& r1,
                                        uint32_t& r2, uint32_t& r3,
                                        const void* p)
{
    uint32_t addr = (uint32_t)__cvta_generic_to_shared(p);
    asm volatile("ldmatrix.sync.aligned.m8n8.x4.shared.b16 {%0,%1,%2,%3}, [%4];"
                 : "=r"(r0), "=r"(r1), "=r"(r2), "=r"(r3) : "r"(addr));
}

__device__ __forceinline__ void mma_bf16(float* c, const uint32_t* a, const uint32_t* b)
{
    asm volatile("mma.sync.aligned.m16n8k16.row.col.f32.bf16.bf16.f32 "
                 "{%0,%1,%2,%3}, {%4,%5,%6,%7}, {%8,%9}, {%0,%1,%2,%3};"
                 : "+f"(c[0]), "+f"(c[1]), "+f"(c[2]), "+f"(c[3])
                 : "r"(a[0]), "r"(a[1]), "r"(a[2]), "r"(a[3]),
                   "r"(b[0]), "r"(b[1]));
}

template<bool RELU>
__global__ __launch_bounds__(256)
void tgemm(const float* __restrict__ A, const float* __restrict__ Bbase,
           const float* __restrict__ bias, float* __restrict__ Cbase,
           int nrows, int M, int K, long strideB, long strideC)
{
    const float* Bg = Bbase + (size_t)blockIdx.z * strideB;
    float*       C  = Cbase + (size_t)blockIdx.z * strideC;

    __shared__ __align__(16) __nv_bfloat16 As[2][128][40];
    __shared__ __align__(16) __nv_bfloat16 Bs[2][128][40];

    const int tid  = threadIdx.x;
    const int lane = tid & 31;
    const int wid  = tid >> 5;
    const int wm   = wid >> 1;
    const int wn   = wid & 1;
    const int row0 = blockIdx.y * 128;
    const int col0 = blockIdx.x * 128;

    float acc[2][8][4];
#pragma unroll
    for (int mt = 0; mt < 2; mt++)
#pragma unroll
        for (int nt = 0; nt < 8; nt++)
#pragma unroll
            for (int i = 0; i < 4; i++) acc[mt][nt][i] = 0.f;

    const int srow = tid >> 1;
    const int skq  = (tid & 1) * 16;

    for (int k0 = 0; k0 < K; k0 += 32) {
        {
            int gr = row0 + srow;
            const float* ap = A + (size_t)gr * K + k0 + skq;
#pragma unroll
            for (int i = 0; i < 4; i++) {
                float4 v = (gr < nrows) ? *(const float4*)(ap + i * 4)
                                        : make_float4(0.f, 0.f, 0.f, 0.f);
                float f[4] = {v.x, v.y, v.z, v.w};
                __nv_bfloat16 h[4], l[4];
#pragma unroll
                for (int j = 0; j < 4; j++) {
                    h[j] = __float2bfloat16_rn(f[j]);
                    l[j] = __float2bfloat16_rn(f[j] - __bfloat162float(h[j]));
                }
                int kk = skq + i * 4;
                *(__nv_bfloat162*)&As[0][srow][kk]     = __halves2bfloat162(h[0], h[1]);
                *(__nv_bfloat162*)&As[0][srow][kk + 2] = __halves2bfloat162(h[2], h[3]);
                *(__nv_bfloat162*)&As[1][srow][kk]     = __halves2bfloat162(l[0], l[1]);
                *(__nv_bfloat162*)&As[1][srow][kk + 2] = __halves2bfloat162(l[2], l[3]);
            }
            const float* bp = Bg + (size_t)(col0 + srow) * K + k0 + skq;
#pragma unroll
            for (int i = 0; i < 4; i++) {
                float4 v = *(const float4*)(bp + i * 4);
                float f[4] = {v.x, v.y, v.z, v.w};
                __nv_bfloat16 h[4], l[4];
#pragma unroll
                for (int j = 0; j < 4; j++) {
                    h[j] = __float2bfloat16_rn(f[j]);
                    l[j] = __float2bfloat16_rn(f[j] - __bfloat162float(h[j]));
                }
                int kk = skq + i * 4;
                *(__nv_bfloat162*)&Bs[0][srow][kk]     = __halves2bfloat162(h[0], h[1]);
                *(__nv_bfloat162*)&Bs[0][srow][kk + 2] = __halves2bfloat162(h[2], h[3]);
                *(__nv_bfloat162*)&Bs[1][srow][kk]     = __halves2bfloat162(l[0], l[1]);
                *(__nv_bfloat162*)&Bs[1][srow][kk + 2] = __halves2bfloat162(l[2], l[3]);
            }
        }
        __syncthreads();

#pragma unroll
        for (int kk = 0; kk < 2; kk++) {
            uint32_t af[2][2][4];
#pragma unroll
            for (int mt = 0; mt < 2; mt++) {
                int r = wm * 32 + mt * 16 + (lane & 15);
                int c = kk * 16 + ((lane >> 4) << 3);
                ldsm_x4(af[0][mt][0], af[0][mt][1], af[0][mt][2], af[0][mt][3], &As[0][r][c]);
                ldsm_x4(af[1][mt][0], af[1][mt][1], af[1][mt][2], af[1][mt][3], &As[1][r][c]);
            }
            uint32_t bfr[2][4][4];
#pragma unroll
            for (int ng = 0; ng < 4; ng++) {
                int r = wn * 64 + ng * 16 + ((lane >> 4) << 3) + (lane & 7);
                int c = kk * 16 + ((lane >> 3) & 1) * 8;
                ldsm_x4(bfr[0][ng][0], bfr[0][ng][1], bfr[0][ng][2], bfr[0][ng][3], &Bs[0][r][c]);
                ldsm_x4(bfr[1][ng][0], bfr[1][ng][1], bfr[1][ng][2], bfr[1][ng][3], &Bs[1][r][c]);
            }
#pragma unroll
            for (int mt = 0; mt < 2; mt++)
#pragma unroll
                for (int ng = 0; ng < 4; ng++)
#pragma unroll
                    for (int h = 0; h < 2; h++) {
                        int nt = ng * 2 + h;
                        mma_bf16(acc[mt][nt], af[0][mt], &bfr[0][ng][h * 2]);
                        mma_bf16(acc[mt][nt], af[0][mt], &bfr[1][ng][h * 2]);
                        mma_bf16(acc[mt][nt], af[1][mt], &bfr[0][ng][h * 2]);
                    }
        }
        __syncthreads();
    }

#pragma unroll
    for (int mt = 0; mt < 2; mt++) {
        int rbase = row0 + wm * 32 + mt * 16 + (lane >> 2);
#pragma unroll
        for (int nt = 0; nt < 8; nt++) {
            int c = col0 + wn * 64 + nt * 8 + (lane & 3) * 2;
            float b0 = bias ? bias[c]     : 0.f;
            float b1 = bias ? bias[c + 1] : 0.f;
            float v0 = acc[mt][nt][0] + b0, v1 = acc[mt][nt][1] + b1;
            float v2 = acc[mt][nt][2] + b0, v3 = acc[mt][nt][3] + b1;
            if (RELU) {
                v0 = fmaxf(v0, 0.f); v1 = fmaxf(v1, 0.f);
                v2 = fmaxf(v2, 0.f); v3 = fmaxf(v3, 0.f);
            }
            if (rbase < nrows)
                *(float2*)&C[(size_t)rbase * M + c] = make_float2(v0, v1);
            if (rbase + 8 < nrows)
                *(float2*)&C[(size_t)(rbase + 8) * M + c] = make_float2(v2, v3);
        }
    }
}

// --------------------------------------------------------------------------
// GRU cell (hidden = x0 always) + relu.
// --------------------------------------------------------------------------
__device__ __forceinline__ float sigm(float x) { return 1.f / (1.f + __expf(-x)); }

__global__ void gru_relu(const float* __restrict__ gi,
                         const float* __restrict__ gh,
                         const float* __restrict__ x0,
                         float* __restrict__ m)
{
    int i = blockIdx.x * blockDim.x + threadIdx.x;
    if (i >= NN * LD) return;
    int n = i >> 7, j = i & 127;
    const float* gin = gi + (size_t)n * 3 * LD;
    const float* ghn = gh + (size_t)n * 3 * LD;
    float r  = sigm(gin[j]          + ghn[j]);
    float z  = sigm(gin[LD + j]     + ghn[LD + j]);
    float ng = tanhf(gin[2 * LD + j] + r * ghn[2 * LD + j]);
    float h  = x0[i];
    float v  = (1.f - z) * ng + z * h;
    m[i] = fmaxf(v, 0.f);
}

// --------------------------------------------------------------------------
extern "C" void kernel_launch(void* const* d_in, const int* in_sizes, int n_in,
                              void* d_out, int out_size)
{
    const float* x     = (const float*)d_in[0];
    const void*  ei    = d_in[1];
    const float* attr  = (const float*)d_in[2];
    const float* lin_w = (const float*)d_in[3];
    const float* lin_b = (const float*)d_in[4];
    const float* gnn_w = (const float*)d_in[5];
    const float* w_ih  = (const float*)d_in[6];
    const float* w_hh  = (const float*)d_in[7];
    const float* b_ih  = (const float*)d_in[8];
    const float* b_hh  = (const float*)d_in[9];
    const float* mu_w  = (const float*)d_in[10];
    const float* mu_b  = (const float*)d_in[11];
    const float* lv_w  = (const float*)d_in[12];
    const float* lv_b  = (const float*)d_in[13];
    float* out = (float*)d_out;

    float *x0, *gh, *aggT, *agg, *gi, *m, *wcat;
    int *src, *dst, *bond, *cnt, *rowptr, *cursor, *packed;
    cudaGetSymbolAddress((void**)&x0,    g_x0);
    cudaGetSymbolAddress((void**)&gh,    g_gh);
    cudaGetSymbolAddress((void**)&aggT,  g_aggT);
    cudaGetSymbolAddress((void**)&agg,   g_agg);
    cudaGetSymbolAddress((void**)&gi,    g_gi);
    cudaGetSymbolAddress((void**)&m,     g_m);
    cudaGetSymbolAddress((void**)&wcat,  g_wcat);
    cudaGetSymbolAddress((void**)&src,   g_src);
    cudaGetSymbolAddress((void**)&dst,   g_dst);
    cudaGetSymbolAddress((void**)&bond,  g_bond);
    cudaGetSymbolAddress((void**)&cnt,   g_cnt);
    cudaGetSymbolAddress((void**)&rowptr,g_rowptr);
    cudaGetSymbolAddress((void**)&cursor,g_cursor);
    cudaGetSymbolAddress((void**)&packed,g_packed);

    const int YB = (NN + 127) / 128;   // 391

    // ---- edge preprocessing + CSR build ----
    cudaMemsetAsync(cnt, 0, NN * sizeof(int));
    prep_edges<<<(EE + 255) / 256, 256>>>(ei, attr, src, dst, bond, cnt);
    scan_counts<<<1, 1024>>>(cnt, rowptr, cursor);
    fill_csr<<<(EE + 255) / 256, 256>>>(src, dst, bond, cursor, packed);
    pack_wcat<<<(NSTEP * LD * 4 * LD + 255) / 256, 256>>>(gnn_w, wcat);

    // x0 = relu(x @ lin_w.T + lin_b)           [N,128], K=64
    tgemm<true ><<<dim3(1, YB, 1), 256>>>(x,  lin_w, lin_b, x0, NN, LD,     INF, 0, 0);
    // gh = x0 @ w_hh.T + b_hh  (loop invariant) [N,384], K=128
    tgemm<false><<<dim3(3, YB, 1), 256>>>(x0, w_hh,  b_hh,  gh, NN, 3 * LD, LD,  0, 0);

    for (int s = 0; s < NSTEP; s++) {
        const float* mIn = (s == 0) ? x0 : m;
        // aggT[d][t] = 2 * sum_{e: dst=d, bond=t} mIn[src_e]   (CSR, no atomics)
        aggregate<<<(NN * 32 + 255) / 256, 256>>>(
            (const float4*)mIn, rowptr, packed, (float4*)aggT);
        // agg = aggT @ Wcat[s].T   [N,128], K=512  (== old per-type H GEMM + segsum)
        tgemm<false><<<dim3(1, YB, 1), 256>>>(
            aggT, wcat + (size_t)s * LD * 4 * LD, nullptr, agg, NN, LD, 4 * LD, 0, 0);
        // gi = agg @ w_ih.T + b_ih   [N,384], K=128
        tgemm<false><<<dim3(3, YB, 1), 256>>>(agg, w_ih, b_ih, gi, NN, 3 * LD, LD, 0, 0);
        gru_relu<<<(NN * LD + 255) / 256, 256>>>(gi, gh, x0, m);
    }

    // mu / logvar heads -> out[0:N*L], out[N*L:2*N*L]
    tgemm<false><<<dim3(1, YB, 1), 256>>>(m, mu_w, mu_b, out,                   NN, LD, LD, 0, 0);
    tgemm<false><<<dim3(1, YB, 1), 256>>>(m, lv_w, lv_b, out + (size_t)NN * LD, NN, LD, LD, 0, 0);
}

// round 17
// speedup vs baseline: 1.8884x; 1.0082x over previous
#include <cuda_runtime.h>
#include <cuda_bf16.h>
#include <cstdint>

#define NN    50000
#define INF   64
#define LD    128
#define NSTEP 3
#define TT    4
#define EE    800000

// -------- scratch (static device globals) ----------------------------------
__device__ __align__(16) float g_x0  [(size_t)NN * LD];
__device__ __align__(16) float g_gh  [(size_t)NN * 3 * LD];
__device__ __align__(16) float g_aggT[(size_t)NN * 4 * LD];   // [d][t*128+j]
__device__ __align__(16) float g_agg [(size_t)NN * LD];
__device__ __align__(16) float g_gi  [(size_t)NN * 3 * LD];
__device__ __align__(16) float g_m   [(size_t)NN * LD];
__device__ __align__(16) float g_wcat[(size_t)NSTEP * LD * 4 * LD]; // [s][i][t*128+j]
__device__ int g_src   [EE];
__device__ int g_dst   [EE];
__device__ int g_bond  [EE];
__device__ int g_cnt   [NN];
__device__ int g_rowptr[NN + 1];
__device__ int g_cursor[NN];
__device__ int g_packed[EE];          // src | (bond<<16)

// --------------------------------------------------------------------------
// Edge preprocessing: dtype-robust index decode, bond argmax, dst histogram.
// --------------------------------------------------------------------------
__global__ void prep_edges(const void* __restrict__ ei_raw,
                           const float* __restrict__ attr,
                           int* __restrict__ src, int* __restrict__ dst,
                           int* __restrict__ bond, int* __restrict__ cnt)
{
    int e = blockIdx.x * blockDim.x + threadIdx.x;
    if (e >= EE) return;

    const int*       ei32 = (const int*)ei_raw;
    const long long* ei64 = (const long long*)ei_raw;

    bool is64 = true;
#pragma unroll
    for (int i = 1; i < 64; i += 2)
        if (ei32[i] != 0) { is64 = false; break; }

    long long s, d;
    if (is64) { s = ei64[e]; d = ei64[(size_t)EE + e]; }
    else      { s = ei32[e]; d = ei32[EE + e]; }
    int si = (s >= 0 && s < NN) ? (int)s : 0;
    int di = (d >= 0 && d < NN) ? (int)d : 0;
    src[e] = si;
    dst[e] = di;

    float4 a = *reinterpret_cast<const float4*>(attr + 4 * (size_t)e);
    int b = 0; float best = a.x;
    if (a.y > best) { best = a.y; b = 1; }
    if (a.z > best) { best = a.z; b = 2; }
    if (a.w > best) { best = a.w; b = 3; }
    bond[e] = b;

    atomicAdd(&cnt[di], 1);
}

// Exclusive scan of per-node counts -> row_ptr (and cursor copy). One block.
__global__ __launch_bounds__(1024)
void scan_counts(const int* __restrict__ cnt, int* __restrict__ row_ptr,
                 int* __restrict__ cursor)
{
    __shared__ int part[1024];
    const int t  = threadIdx.x;
    const int CH = (NN + 1023) / 1024;
    int lo = t * CH;
    int hi = lo + CH; if (hi > NN) hi = NN; if (lo > NN) lo = NN;

    int s = 0;
    for (int i = lo; i < hi; i++) s += cnt[i];
    part[t] = s;
    __syncthreads();
    for (int off = 1; off < 1024; off <<= 1) {
        int v = (t >= off) ? part[t - off] : 0;
        __syncthreads();
        part[t] += v;
        __syncthreads();
    }
    int run = (t == 0) ? 0 : part[t - 1];
    for (int i = lo; i < hi; i++) {
        row_ptr[i] = run; cursor[i] = run; run += cnt[i];
    }
    if (t == 1023) row_ptr[NN] = part[1023];
}

__global__ void fill_csr(const int* __restrict__ src, const int* __restrict__ dst,
                         const int* __restrict__ bond, int* __restrict__ cursor,
                         int* __restrict__ packed)
{
    int e = blockIdx.x * blockDim.x + threadIdx.x;
    if (e >= EE) return;
    int pos = atomicAdd(&cursor[dst[e]], 1);
    packed[pos] = src[e] | (bond[e] << 16);
}

// Pack gnn_w [s][t][i][j] -> wcat [s][i][t*128+j] (B operand, row-major, K=512)
__global__ void pack_wcat(const float* __restrict__ gnn_w, float* __restrict__ wcat)
{
    int i = blockIdx.x * blockDim.x + threadIdx.x;
    if (i >= NSTEP * LD * 4 * LD) return;
    int s = i / (LD * 4 * LD);
    int r = (i / (4 * LD)) % LD;
    int k = i % (4 * LD);
    int t = k / LD, j = k % LD;
    wcat[i] = gnn_w[(((size_t)s * TT + t) * LD + r) * LD + j];
}

// --------------------------------------------------------------------------
// CSR aggregation, MLP-unrolled x4: one warp per dst node. Four edge rows
// are fetched concurrently (independent LDG.128s) before the warp-uniform
// branchy accumulate, hiding L2 latency. x2 edge-dup factor folded in.
// --------------------------------------------------------------------------
__global__ void aggregate(const float4* __restrict__ m4,
                          const int* __restrict__ row_ptr,
                          const int* __restrict__ packed,
                          float4* __restrict__ aggT4)
{
    int w    = (blockIdx.x * blockDim.x + threadIdx.x) >> 5;
    int lane = threadIdx.x & 31;
    if (w >= NN) return;
    int e0 = row_ptr[w], e1 = row_ptr[w + 1];

    float4 a0 = {0,0,0,0}, a1 = {0,0,0,0}, a2 = {0,0,0,0}, a3 = {0,0,0,0};

#define ACC_EDGE(P, V)                                                        \
    {   int _b = (P) >> 16;                                                   \
        if      (_b == 0) { a0.x += (V).x; a0.y += (V).y; a0.z += (V).z; a0.w += (V).w; } \
        else if (_b == 1) { a1.x += (V).x; a1.y += (V).y; a1.z += (V).z; a1.w += (V).w; } \
        else if (_b == 2) { a2.x += (V).x; a2.y += (V).y; a2.z += (V).z; a2.w += (V).w; } \
        else              { a3.x += (V).x; a3.y += (V).y; a3.z += (V).z; a3.w += (V).w; } }

    for (int base = e0; base < e1; base += 32) {
        int idx = base + lane;
        int pe  = (idx < e1) ? packed[idx] : 0;
        int nb  = e1 - base; if (nb > 32) nb = 32;

        int i = 0;
        for (; i + 4 <= nb; i += 4) {
            int p0 = __shfl_sync(0xffffffffu, pe, i);
            int p1 = __shfl_sync(0xffffffffu, pe, i + 1);
            int p2 = __shfl_sync(0xffffffffu, pe, i + 2);
            int p3 = __shfl_sync(0xffffffffu, pe, i + 3);
            // four independent row loads in flight (MLP=4)
            float4 v0 = m4[(size_t)(p0 & 0xffff) * 32 + lane];
            float4 v1 = m4[(size_t)(p1 & 0xffff) * 32 + lane];
            float4 v2 = m4[(size_t)(p2 & 0xffff) * 32 + lane];
            float4 v3 = m4[(size_t)(p3 & 0xffff) * 32 + lane];
            ACC_EDGE(p0, v0);
            ACC_EDGE(p1, v1);
            ACC_EDGE(p2, v2);
            ACC_EDGE(p3, v3);
        }
        for (; i < nb; i++) {
            int p = __shfl_sync(0xffffffffu, pe, i);
            float4 v = m4[(size_t)(p & 0xffff) * 32 + lane];
            ACC_EDGE(p, v);
        }
    }
#undef ACC_EDGE

    float4* o = aggT4 + (size_t)w * 128;    // 512 floats = 128 float4
    o[lane]      = make_float4(2.f*a0.x, 2.f*a0.y, 2.f*a0.z, 2.f*a0.w);
    o[32 + lane] = make_float4(2.f*a1.x, 2.f*a1.y, 2.f*a1.z, 2.f*a1.w);
    o[64 + lane] = make_float4(2.f*a2.x, 2.f*a2.y, 2.f*a2.z, 2.f*a2.w);
    o[96 + lane] = make_float4(2.f*a3.x, 2.f*a3.y, 2.f*a3.z, 2.f*a3.w);
}

// --------------------------------------------------------------------------
// Tensor-core GEMM: C = act(A @ B^T + bias), split-bf16 (3-term). Unchanged.
// --------------------------------------------------------------------------
__device__ __forceinline__ void ldsm_x4(uint32_t& r0, uint32_t& r1,
                                        uint32_t& r2, uint32_t& r3,
                                        const void* p)
{
    uint32_t addr = (uint32_t)__cvta_generic_to_shared(p);
    asm volatile("ldmatrix.sync.aligned.m8n8.x4.shared.b16 {%0,%1,%2,%3}, [%4];"
                 : "=r"(r0), "=r"(r1), "=r"(r2), "=r"(r3) : "r"(addr));
}

__device__ __forceinline__ void mma_bf16(float* c, const uint32_t* a, const uint32_t* b)
{
    asm volatile("mma.sync.aligned.m16n8k16.row.col.f32.bf16.bf16.f32 "
                 "{%0,%1,%2,%3}, {%4,%5,%6,%7}, {%8,%9}, {%0,%1,%2,%3};"
                 : "+f"(c[0]), "+f"(c[1]), "+f"(c[2]), "+f"(c[3])
                 : "r"(a[0]), "r"(a[1]), "r"(a[2]), "r"(a[3]),
                   "r"(b[0]), "r"(b[1]));
}

template<bool RELU>
__global__ __launch_bounds__(256)
void tgemm(const float* __restrict__ A, const float* __restrict__ Bbase,
           const float* __restrict__ bias, float* __restrict__ Cbase,
           int nrows, int M, int K, long strideB, long strideC)
{
    const float* Bg = Bbase + (size_t)blockIdx.z * strideB;
    float*       C  = Cbase + (size_t)blockIdx.z * strideC;

    __shared__ __align__(16) __nv_bfloat16 As[2][128][40];
    __shared__ __align__(16) __nv_bfloat16 Bs[2][128][40];

    const int tid  = threadIdx.x;
    const int lane = tid & 31;
    const int wid  = tid >> 5;
    const int wm   = wid >> 1;
    const int wn   = wid & 1;
    const int row0 = blockIdx.y * 128;
    const int col0 = blockIdx.x * 128;

    float acc[2][8][4];
#pragma unroll
    for (int mt = 0; mt < 2; mt++)
#pragma unroll
        for (int nt = 0; nt < 8; nt++)
#pragma unroll
            for (int i = 0; i < 4; i++) acc[mt][nt][i] = 0.f;

    const int srow = tid >> 1;
    const int skq  = (tid & 1) * 16;

    for (int k0 = 0; k0 < K; k0 += 32) {
        {
            int gr = row0 + srow;
            const float* ap = A + (size_t)gr * K + k0 + skq;
#pragma unroll
            for (int i = 0; i < 4; i++) {
                float4 v = (gr < nrows) ? *(const float4*)(ap + i * 4)
                                        : make_float4(0.f, 0.f, 0.f, 0.f);
                float f[4] = {v.x, v.y, v.z, v.w};
                __nv_bfloat16 h[4], l[4];
#pragma unroll
                for (int j = 0; j < 4; j++) {
                    h[j] = __float2bfloat16_rn(f[j]);
                    l[j] = __float2bfloat16_rn(f[j] - __bfloat162float(h[j]));
                }
                int kk = skq + i * 4;
                *(__nv_bfloat162*)&As[0][srow][kk]     = __halves2bfloat162(h[0], h[1]);
                *(__nv_bfloat162*)&As[0][srow][kk + 2] = __halves2bfloat162(h[2], h[3]);
                *(__nv_bfloat162*)&As[1][srow][kk]     = __halves2bfloat162(l[0], l[1]);
                *(__nv_bfloat162*)&As[1][srow][kk + 2] = __halves2bfloat162(l[2], l[3]);
            }
            const float* bp = Bg + (size_t)(col0 + srow) * K + k0 + skq;
#pragma unroll
            for (int i = 0; i < 4; i++) {
                float4 v = *(const float4*)(bp + i * 4);
                float f[4] = {v.x, v.y, v.z, v.w};
                __nv_bfloat16 h[4], l[4];
#pragma unroll
                for (int j = 0; j < 4; j++) {
                    h[j] = __float2bfloat16_rn(f[j]);
                    l[j] = __float2bfloat16_rn(f[j] - __bfloat162float(h[j]));
                }
                int kk = skq + i * 4;
                *(__nv_bfloat162*)&Bs[0][srow][kk]     = __halves2bfloat162(h[0], h[1]);
                *(__nv_bfloat162*)&Bs[0][srow][kk + 2] = __halves2bfloat162(h[2], h[3]);
                *(__nv_bfloat162*)&Bs[1][srow][kk]     = __halves2bfloat162(l[0], l[1]);
                *(__nv_bfloat162*)&Bs[1][srow][kk + 2] = __halves2bfloat162(l[2], l[3]);
            }
        }
        __syncthreads();

#pragma unroll
        for (int kk = 0; kk < 2; kk++) {
            uint32_t af[2][2][4];
#pragma unroll
            for (int mt = 0; mt < 2; mt++) {
                int r = wm * 32 + mt * 16 + (lane & 15);
                int c = kk * 16 + ((lane >> 4) << 3);
                ldsm_x4(af[0][mt][0], af[0][mt][1], af[0][mt][2], af[0][mt][3], &As[0][r][c]);
                ldsm_x4(af[1][mt][0], af[1][mt][1], af[1][mt][2], af[1][mt][3], &As[1][r][c]);
            }
            uint32_t bfr[2][4][4];
#pragma unroll
            for (int ng = 0; ng < 4; ng++) {
                int r = wn * 64 + ng * 16 + ((lane >> 4) << 3) + (lane & 7);
                int c = kk * 16 + ((lane >> 3) & 1) * 8;
                ldsm_x4(bfr[0][ng][0], bfr[0][ng][1], bfr[0][ng][2], bfr[0][ng][3], &Bs[0][r][c]);
                ldsm_x4(bfr[1][ng][0], bfr[1][ng][1], bfr[1][ng][2], bfr[1][ng][3], &Bs[1][r][c]);
            }
#pragma unroll
            for (int mt = 0; mt < 2; mt++)
#pragma unroll
                for (int ng = 0; ng < 4; ng++)
#pragma unroll
                    for (int h = 0; h < 2; h++) {
                        int nt = ng * 2 + h;
                        mma_bf16(acc[mt][nt], af[0][mt], &bfr[0][ng][h * 2]);
                        mma_bf16(acc[mt][nt], af[0][mt], &bfr[1][ng][h * 2]);
                        mma_bf16(acc[mt][nt], af[1][mt], &bfr[0][ng][h * 2]);
                    }
        }
        __syncthreads();
    }

#pragma unroll
    for (int mt = 0; mt < 2; mt++) {
        int rbase = row0 + wm * 32 + mt * 16 + (lane >> 2);
#pragma unroll
        for (int nt = 0; nt < 8; nt++) {
            int c = col0 + wn * 64 + nt * 8 + (lane & 3) * 2;
            float b0 = bias ? bias[c]     : 0.f;
            float b1 = bias ? bias[c + 1] : 0.f;
            float v0 = acc[mt][nt][0] + b0, v1 = acc[mt][nt][1] + b1;
            float v2 = acc[mt][nt][2] + b0, v3 = acc[mt][nt][3] + b1;
            if (RELU) {
                v0 = fmaxf(v0, 0.f); v1 = fmaxf(v1, 0.f);
                v2 = fmaxf(v2, 0.f); v3 = fmaxf(v3, 0.f);
            }
            if (rbase < nrows)
                *(float2*)&C[(size_t)rbase * M + c] = make_float2(v0, v1);
            if (rbase + 8 < nrows)
                *(float2*)&C[(size_t)(rbase + 8) * M + c] = make_float2(v2, v3);
        }
    }
}

// --------------------------------------------------------------------------
// GRU cell (hidden = x0 always) + relu.
// --------------------------------------------------------------------------
__device__ __forceinline__ float sigm(float x) { return 1.f / (1.f + __expf(-x)); }

__global__ void gru_relu(const float* __restrict__ gi,
                         const float* __restrict__ gh,
                         const float* __restrict__ x0,
                         float* __restrict__ m)
{
    int i = blockIdx.x * blockDim.x + threadIdx.x;
    if (i >= NN * LD) return;
    int n = i >> 7, j = i & 127;
    const float* gin = gi + (size_t)n * 3 * LD;
    const float* ghn = gh + (size_t)n * 3 * LD;
    float r  = sigm(gin[j]          + ghn[j]);
    float z  = sigm(gin[LD + j]     + ghn[LD + j]);
    float ng = tanhf(gin[2 * LD + j] + r * ghn[2 * LD + j]);
    float h  = x0[i];
    float v  = (1.f - z) * ng + z * h;
    m[i] = fmaxf(v, 0.f);
}

// --------------------------------------------------------------------------
extern "C" void kernel_launch(void* const* d_in, const int* in_sizes, int n_in,
                              void* d_out, int out_size)
{
    const float* x     = (const float*)d_in[0];
    const void*  ei    = d_in[1];
    const float* attr  = (const float*)d_in[2];
    const float* lin_w = (const float*)d_in[3];
    const float* lin_b = (const float*)d_in[4];
    const float* gnn_w = (const float*)d_in[5];
    const float* w_ih  = (const float*)d_in[6];
    const float* w_hh  = (const float*)d_in[7];
    const float* b_ih  = (const float*)d_in[8];
    const float* b_hh  = (const float*)d_in[9];
    const float* mu_w  = (const float*)d_in[10];
    const float* mu_b  = (const float*)d_in[11];
    const float* lv_w  = (const float*)d_in[12];
    const float* lv_b  = (const float*)d_in[13];
    float* out = (float*)d_out;

    float *x0, *gh, *aggT, *agg, *gi, *m, *wcat;
    int *src, *dst, *bond, *cnt, *rowptr, *cursor, *packed;
    cudaGetSymbolAddress((void**)&x0,    g_x0);
    cudaGetSymbolAddress((void**)&gh,    g_gh);
    cudaGetSymbolAddress((void**)&aggT,  g_aggT);
    cudaGetSymbolAddress((void**)&agg,   g_agg);
    cudaGetSymbolAddress((void**)&gi,    g_gi);
    cudaGetSymbolAddress((void**)&m,     g_m);
    cudaGetSymbolAddress((void**)&wcat,  g_wcat);
    cudaGetSymbolAddress((void**)&src,   g_src);
    cudaGetSymbolAddress((void**)&dst,   g_dst);
    cudaGetSymbolAddress((void**)&bond,  g_bond);
    cudaGetSymbolAddress((void**)&cnt,   g_cnt);
    cudaGetSymbolAddress((void**)&rowptr,g_rowptr);
    cudaGetSymbolAddress((void**)&cursor,g_cursor);
    cudaGetSymbolAddress((void**)&packed,g_packed);

    const int YB = (NN + 127) / 128;   // 391

    // ---- edge preprocessing + CSR build ----
    cudaMemsetAsync(cnt, 0, NN * sizeof(int));
    prep_edges<<<(EE + 255) / 256, 256>>>(ei, attr, src, dst, bond, cnt);
    scan_counts<<<1, 1024>>>(cnt, rowptr, cursor);
    fill_csr<<<(EE + 255) / 256, 256>>>(src, dst, bond, cursor, packed);
    pack_wcat<<<(NSTEP * LD * 4 * LD + 255) / 256, 256>>>(gnn_w, wcat);

    // x0 = relu(x @ lin_w.T + lin_b)           [N,128], K=64
    tgemm<true ><<<dim3(1, YB, 1), 256>>>(x,  lin_w, lin_b, x0, NN, LD,     INF, 0, 0);
    // gh = x0 @ w_hh.T + b_hh  (loop invariant) [N,384], K=128
    tgemm<false><<<dim3(3, YB, 1), 256>>>(x0, w_hh,  b_hh,  gh, NN, 3 * LD, LD,  0, 0);

    for (int s = 0; s < NSTEP; s++) {
        const float* mIn = (s == 0) ? x0 : m;
        // aggT[d][t] = 2 * sum_{e: dst=d, bond=t} mIn[src_e]   (CSR, MLP x4)
        aggregate<<<(NN * 32 + 255) / 256, 256>>>(
            (const float4*)mIn, rowptr, packed, (float4*)aggT);
        // agg = aggT @ Wcat[s].T   [N,128], K=512
        tgemm<false><<<dim3(1, YB, 1), 256>>>(
            aggT, wcat + (size_t)s * LD * 4 * LD, nullptr, agg, NN, LD, 4 * LD, 0, 0);
        // gi = agg @ w_ih.T + b_ih   [N,384], K=128
        tgemm<false><<<dim3(3, YB, 1), 256>>>(agg, w_ih, b_ih, gi, NN, 3 * LD, LD, 0, 0);
        gru_relu<<<(NN * LD + 255) / 256, 256>>>(gi, gh, x0, m);
    }

    // mu / logvar heads -> out[0:N*L], out[N*L:2*N*L]
    tgemm<false><<<dim3(1, YB, 1), 256>>>(m, mu_w, mu_b, out,                   NN, LD, LD, 0, 0);
    tgemm<false><<<dim3(1, YB, 1), 256>>>(m, lv_w, lv_b, out + (size_t)NN * LD, NN, LD, LD, 0, 0);
}